// round 14
// baseline (speedup 1.0000x reference)
#include <cuda_runtime.h>
#include <cuda_bf16.h>
#include <cuda_fp16.h>
#include <math.h>
#include <stdint.h>

#define BATCH 64
#define HD    1024
#define ED    1024
#define VOC   32000
#define TT    50
#define G4    (4*HD)
#define START_IDX 1

// row padded to 72 halves = 144 bytes (16B-aligned, conflict-free ldmatrix)
#define RP 72

// ---------------- device scratch ----------------
__device__ __align__(128) __nv_bfloat16 g_WB1[(size_t)128*32*2*32*RP];
__device__ __align__(128) __half        g_Wo16blk[(size_t)125*16*256*RP];
__device__ __align__(128) __nv_bfloat16 g_hblk[(size_t)2*16*2*64*RP];
__device__ __align__(128) __half        g_h16blk[(size_t)16*64*RP];
__device__ __align__(128) __nv_bfloat16 g_xblk[(size_t)16*2*64*RP];
__device__ float    g_c[BATCH*HD];
__device__ float    g_sum[BATCH];
__device__ unsigned g_maxe[BATCH];
__device__ int      g_cand[BATCH][32];
__device__ int      g_ncand[BATCH];
__device__ unsigned g_k2cnt;

// ---------------- asm helpers ----------------
__device__ __forceinline__ void mma_bf(float* c, const uint32_t* a, uint32_t b0, uint32_t b1) {
    asm volatile(
        "mma.sync.aligned.m16n8k16.row.col.f32.bf16.bf16.f32 "
        "{%0,%1,%2,%3}, {%4,%5,%6,%7}, {%8,%9}, {%0,%1,%2,%3};\n"
        : "+f"(c[0]), "+f"(c[1]), "+f"(c[2]), "+f"(c[3])
        : "r"(a[0]), "r"(a[1]), "r"(a[2]), "r"(a[3]), "r"(b0), "r"(b1));
}
__device__ __forceinline__ void mma_f16(float* c, const uint32_t* a, uint32_t b0, uint32_t b1) {
    asm volatile(
        "mma.sync.aligned.m16n8k16.row.col.f32.f16.f16.f32 "
        "{%0,%1,%2,%3}, {%4,%5,%6,%7}, {%8,%9}, {%0,%1,%2,%3};\n"
        : "+f"(c[0]), "+f"(c[1]), "+f"(c[2]), "+f"(c[3])
        : "r"(a[0]), "r"(a[1]), "r"(a[2]), "r"(a[3]), "r"(b0), "r"(b1));
}
__device__ __forceinline__ void ldsm4(uint32_t* r, uint32_t addr) {
    asm volatile("ldmatrix.sync.aligned.m8n8.x4.shared.b16 {%0,%1,%2,%3}, [%4];\n"
        : "=r"(r[0]), "=r"(r[1]), "=r"(r[2]), "=r"(r[3]) : "r"(addr));
}
__device__ __forceinline__ void bulk_g2s(uint32_t dst, const void* src, uint32_t bytes, uint32_t mbar) {
    asm volatile("cp.async.bulk.shared::cluster.global.mbarrier::complete_tx::bytes [%0], [%1], %2, [%3];\n"
        :: "r"(dst), "l"(src), "r"(bytes), "r"(mbar) : "memory");
}
__device__ __forceinline__ void mbar_init(uint32_t a, uint32_t cnt) {
    asm volatile("mbarrier.init.shared.b64 [%0], %1;" :: "r"(a), "r"(cnt) : "memory");
}
__device__ __forceinline__ void mbar_expect(uint32_t a, uint32_t bytes) {
    asm volatile("mbarrier.arrive.expect_tx.shared.b64 _, [%0], %1;" :: "r"(a), "r"(bytes) : "memory");
}
__device__ __forceinline__ void mbar_wait(uint32_t a, uint32_t parity) {
    asm volatile(
        "{\n\t"
        ".reg .pred P1;\n\t"
        "WAIT_%=:\n\t"
        "mbarrier.try_wait.parity.acquire.cta.shared::cta.b64 P1, [%0], %1, 0x989680;\n\t"
        "@P1 bra.uni DONE_%=;\n\t"
        "bra.uni WAIT_%=;\n\t"
        "DONE_%=:\n\t"
        "}"
        :: "r"(a), "r"(parity) : "memory");
}
__device__ __forceinline__ void fence_async_init() {
    asm volatile("fence.proxy.async.shared::cta;" ::: "memory");
}

// FMA-only exp. rel err ~1.2e-7.
__device__ __forceinline__ float fast_exp(float x) {
    float t = x * 1.4426950408889634f;
    t = fmaxf(t, -120.0f);
    float n = rintf(t);
    float r = (t - n) * 0.6931471805599453f;
    float p = 1.0f / 5040.0f;
    p = fmaf(p, r, 1.0f / 720.0f);
    p = fmaf(p, r, 1.0f / 120.0f);
    p = fmaf(p, r, 1.0f / 24.0f);
    p = fmaf(p, r, 1.0f / 6.0f);
    p = fmaf(p, r, 0.5f);
    p = fmaf(p, r, 1.0f);
    p = fmaf(p, r, 1.0f);
    float s = __int_as_float(((int)n + 127) << 23);
    return p * s;
}

// ---------------- one-time weight prep ----------------
__global__ void split_kernel(const float* __restrict__ src, int which, int n) {
    int i = blockIdx.x * blockDim.x + threadIdx.x;
    int stride = gridDim.x * blockDim.x;
    if (which == 3) {          // W_out -> fp16 blocked [nb][chunk][256][RP]
        for (; i < n; i += stride) {
            int v = i >> 10, k = i & 1023;
            int nb = v >> 8, r = v & 255;
            size_t dst = ((size_t)(nb * 16 + (k >> 6)) * 256 + r) * RP
                       + ((k >> 3) & 7) * 8 + (k & 7);
            g_Wo16blk[dst] = __float2half(src[i]);
        }
    } else {                   // W_ih (1) / W_hh (2) -> bf16 hi/lo blocked
        const int cbase = (which == 1) ? 0 : 16;
        for (; i < n; i += stride) {
            int g = i >> 10, k = i & 1023;
            int gate = g >> 10, unit = g & 1023;
            int ublk = unit >> 3, rowB = (gate << 3) | (unit & 7);
            int c = cbase + (k >> 6);
            size_t baseidx = (((size_t)ublk * 32 + c) * 2) * (32 * RP)
                           + rowB * RP + ((k >> 3) & 7) * 8 + (k & 7);
            float w = src[i];
            __nv_bfloat16 h = __float2bfloat16(w);
            g_WB1[baseidx] = h;
            g_WB1[baseidx + 32 * RP] = __float2bfloat16(w - __bfloat162float(h));
        }
    }
}

__global__ void init_kernel(const float* __restrict__ hidden, const float* __restrict__ emb) {
    int i = blockIdx.x * blockDim.x + threadIdx.x;
    if (i == 0) g_k2cnt = 0u;
    if (i < BATCH) { g_sum[i] = 0.0f; g_maxe[i] = 0u; g_ncand[i] = 0; }
    if (i < BATCH * HD) {
        int b = i >> 10, u = i & 1023;
        const int seg = ((u >> 3) & 7) * 8 + (u & 7);
        {
            float h = hidden[i];
            __nv_bfloat16 hh = __float2bfloat16(h);
            size_t idx = (((size_t)(u >> 6)) * 2) * (64 * RP) + (size_t)b * RP + seg;
            g_hblk[idx] = hh;
            g_hblk[idx + 64 * RP] = __float2bfloat16(h - __bfloat162float(hh));
        }
        {
            float w = emb[(size_t)START_IDX * ED + u];
            __nv_bfloat16 hh = __float2bfloat16(w);
            size_t idx = (((size_t)(u >> 6)) * 2) * (64 * RP) + (size_t)b * RP + seg;
            g_xblk[idx] = hh;
            g_xblk[idx + 64 * RP] = __float2bfloat16(w - __bfloat162float(hh));
        }
        g_c[i] = 0.0f;
    }
}

// ---------------- K1: gates GEMM + LSTM cell (256 thr, chunk=64, 3-stage, PDL) --
// stage layout (bytes): A(hi|lo) 18432 | B(hi|lo) 9216 = 27648 -> 3 stages = 83 KB
#define K1_STAGE 27648
__global__ __launch_bounds__(256) void gates_kernel(
        const float* __restrict__ b_ih, const float* __restrict__ b_hh,
        int rd, int wb) {
    extern __shared__ __align__(128) char dynsm[];
    const uint32_t base = (uint32_t)__cvta_generic_to_shared(dynsm);
    __shared__ float Cs[64][33];

    const int tid = threadIdx.x;
    const int ublk = blockIdx.x;
    const int u0 = ublk * 8;
    if (tid == 0) {
        mbar_init(base + 0, 1);
        mbar_init(base + 8, 1);
        mbar_init(base + 16, 1);
    }
    fence_async_init();
    __syncthreads();

    const int lane = tid & 31, wid = tid >> 5;
    const int gq = lane >> 2, cq = lane & 3;
    const int wm = wid & 3, wn = wid >> 2;
    const int lt = lane >> 3, lr = lane & 7;

    float acc[2][4];
#pragma unroll
    for (int i = 0; i < 2; i++)
#pragma unroll
        for (int j = 0; j < 4; j++) acc[i][j] = 0.0f;

    auto issueB = [&](int c, int s) {
        const uint32_t st = base + 64u + (uint32_t)s * K1_STAGE;
        bulk_g2s(st + 18432u,
                 (const char*)g_WB1 + ((size_t)(ublk * 32 + c)) * 9216u,
                 9216u, base + (uint32_t)s * 8u);
    };
    auto issueA = [&](int c, int s) {
        const uint32_t st = base + 64u + (uint32_t)s * K1_STAGE;
        const char* asrc = (c < 16)
            ? (const char*)g_xblk + (size_t)c * 18432u
            : (const char*)g_hblk + ((size_t)(rd * 16 + (c - 16))) * 18432u;
        bulk_g2s(st, asrc, 18432u, base + (uint32_t)s * 8u);
    };
    auto issue = [&](int c, int s) {
        mbar_expect(base + (uint32_t)s * 8u, 27648u);
        issueA(c, s);
        issueB(c, s);
    };

    const int NIT = 32;
    if (tid == 0) {
#pragma unroll
        for (int s = 0; s < 3; s++) {
            mbar_expect(base + (uint32_t)s * 8u, 27648u);
            issueB(s, s);
        }
    }
    cudaGridDependencySynchronize();
    if (tid == 0) {
#pragma unroll
        for (int s = 0; s < 3; s++) issueA(s, s);
    }

    const int a_row = wm * 16 + ((lt & 1) << 3) + lr;
    const int a_sh  = lt >> 1;

    for (int it = 0; it < NIT; it++) {
        const int s = it % 3;
        mbar_wait(base + (uint32_t)s * 8u, (uint32_t)((it / 3) & 1));

        const uint32_t st = base + 64u + (uint32_t)s * K1_STAGE;
        const uint32_t Ahb = st, Alb = st + 9216u, Bhb = st + 18432u, Blb = st + 23040u;
        const uint32_t aoff = (uint32_t)(a_row * 144);

#pragma unroll
        for (int ktp = 0; ktp < 2; ktp++) {
            uint32_t h0[4], h1[4], l0[4], l1[4];
            const uint32_t s0 = (uint32_t)((4 * ktp + a_sh) * 16);
            const uint32_t s1 = (uint32_t)((4 * ktp + 2 + a_sh) * 16);
            ldsm4(h0, Ahb + aoff + s0);
            ldsm4(h1, Ahb + aoff + s1);
            ldsm4(l0, Alb + aoff + s0);
            ldsm4(l1, Alb + aoff + s1);
#pragma unroll
            for (int nt = 0; nt < 2; nt++) {
                const int rowB = wn * 16 + nt * 8 + lr;
                const uint32_t boff = (uint32_t)(rowB * 144 + (ktp * 4 + lt) * 16);
                uint32_t bh[4], bl[4];
                ldsm4(bh, Bhb + boff);
                ldsm4(bl, Blb + boff);
                mma_bf(acc[nt], h0, bh[0], bh[1]);
                mma_bf(acc[nt], l0, bh[0], bh[1]);
                mma_bf(acc[nt], h0, bl[0], bl[1]);
                mma_bf(acc[nt], h1, bh[2], bh[3]);
                mma_bf(acc[nt], l1, bh[2], bh[3]);
                mma_bf(acc[nt], h1, bl[2], bl[3]);
            }
        }
        __syncthreads();
        if (it + 3 < NIT && tid == 0) issue(it + 3, s);
    }

    {
        const int m0 = wm * 16 + gq;
#pragma unroll
        for (int nt = 0; nt < 2; nt++) {
            const int nc = wn * 16 + nt * 8 + 2 * cq;
            Cs[m0][nc]         = acc[nt][0];
            Cs[m0][nc + 1]     = acc[nt][1];
            Cs[m0 + 8][nc]     = acc[nt][2];
            Cs[m0 + 8][nc + 1] = acc[nt][3];
        }
    }
    __syncthreads();

    for (int r = tid; r < 64 * 8; r += 256) {
        const int b = r >> 3, uu = r & 7;
        const int u = u0 + uu;
        float iv = Cs[b][uu]      + b_ih[u]          + b_hh[u];
        float fv = Cs[b][8 + uu]  + b_ih[HD + u]     + b_hh[HD + u];
        float gv = Cs[b][16 + uu] + b_ih[2 * HD + u] + b_hh[2 * HD + u];
        float ov = Cs[b][24 + uu] + b_ih[3 * HD + u] + b_hh[3 * HD + u];
        float co = g_c[b * HD + u];
        float si = 1.0f / (1.0f + expf(-iv));
        float sf = 1.0f / (1.0f + expf(-fv));
        float so = 1.0f / (1.0f + expf(-ov));
        float cn = sf * co + si * tanhf(gv);
        float hn = so * tanhf(cn);
        g_c[b * HD + u] = cn;
        __nv_bfloat16 hh = __float2bfloat16(hn);
        const int seg = ((u >> 3) & 7) * 8 + (u & 7);
        const size_t hbase = (((size_t)(wb * 16 + (u >> 6))) * 2) * (64 * RP) + (size_t)b * RP + seg;
        g_hblk[hbase] = hh;
        g_hblk[hbase + 64 * RP] = __float2bfloat16(hn - __bfloat162float(hh));
        g_h16blk[((size_t)(u >> 6) * 64 + b) * RP + seg] = __float2half(hn);
    }
    cudaTriggerProgrammaticLaunchCompletion();
}

// ------- K2: logits GEMM + full softmax (spin-converged) + candidates (PDL) -----
// 125 blocks x N=256, chunk 64, 2-stage. stage: A 9216 | B 36864 = 46080 -> 92 KB
#define K2_STAGE 46080
__global__ __launch_bounds__(256) void logits_kernel(
        const float* __restrict__ b_out, float* __restrict__ out, int t) {
    extern __shared__ __align__(128) char dynsm2[];
    const uint32_t base = (uint32_t)__cvta_generic_to_shared(dynsm2);
    __shared__ float    ssum[64];
    __shared__ unsigned smax[64];

    const int tid = threadIdx.x;
    const int nb = blockIdx.x;
    const int n0 = nb * 256;
    const int lane = tid & 31, wid = tid >> 5;
    const int gq = lane >> 2, cq = lane & 3;
    const int wm = wid & 3, wn = wid >> 2;
    const int lt = lane >> 3, lr = lane & 7;

    if (tid == 0) {
        mbar_init(base + 0, 1);
        mbar_init(base + 8, 1);
    }
    if (tid < 64) { ssum[tid] = 0.0f; smax[tid] = 0u; }
    fence_async_init();
    __syncthreads();

    float acc[16][4];
#pragma unroll
    for (int i = 0; i < 16; i++)
#pragma unroll
        for (int j = 0; j < 4; j++) acc[i][j] = 0.0f;

    auto issueW = [&](int c, int s) {
        const uint32_t st = base + 64u + (uint32_t)s * K2_STAGE;
        bulk_g2s(st + 9216u,
                 (const char*)g_Wo16blk + ((size_t)(nb * 16 + c) * 256 * RP) * 2,
                 36864u, base + (uint32_t)s * 8u);
    };
    auto issueH = [&](int c, int s) {
        const uint32_t st = base + 64u + (uint32_t)s * K2_STAGE;
        bulk_g2s(st, (const char*)g_h16blk + ((size_t)c * 64 * RP) * 2,
                 9216u, base + (uint32_t)s * 8u);
    };
    auto issue = [&](int c, int s) {
        mbar_expect(base + (uint32_t)s * 8u, 46080u);
        issueH(c, s);
        issueW(c, s);
    };

    const int NIT = 16;
    if (tid == 0) {
#pragma unroll
        for (int s = 0; s < 2; s++) {
            mbar_expect(base + (uint32_t)s * 8u, 46080u);
            issueW(s, s);
        }
    }
    cudaGridDependencySynchronize();
    if (tid == 0) {
#pragma unroll
        for (int s = 0; s < 2; s++) issueH(s, s);
    }

    const int a_row = wm * 16 + ((lt & 1) << 3) + lr;
    const int a_sh  = lt >> 1;

    for (int it = 0; it < NIT; it++) {
        const int s = it & 1;
        mbar_wait(base + (uint32_t)s * 8u, (uint32_t)((it / 2) & 1));

        const uint32_t Ab = base + 64u + (uint32_t)s * K2_STAGE;
        const uint32_t Bb = Ab + 9216u;
        const uint32_t aoff = (uint32_t)(a_row * 144);

#pragma unroll
        for (int ktp = 0; ktp < 2; ktp++) {
            uint32_t a0[4], a1[4];
            ldsm4(a0, Ab + aoff + (uint32_t)((4 * ktp + a_sh) * 16));
            ldsm4(a1, Ab + aoff + (uint32_t)((4 * ktp + 2 + a_sh) * 16));
#pragma unroll
            for (int nt = 0; nt < 16; nt++) {
                const int rowB = wn * 128 + nt * 8 + lr;
                uint32_t b[4];
                ldsm4(b, Bb + (uint32_t)(rowB * 144 + (ktp * 4 + lt) * 16));
                mma_f16(acc[nt], a0, b[0], b[1]);
                mma_f16(acc[nt], a1, b[2], b[3]);
            }
        }
        __syncthreads();
        if (it + 2 < NIT && tid == 0) issue(it + 2, s);
    }

    // epilogue part 1: e = exp(logit) kept in registers; per-row block reduction
    const int m0 = wm * 16 + gq;
    float s0 = 0.0f, s1 = 0.0f;
    float m0v = 0.0f, m1v = 0.0f;
#pragma unroll
    for (int nt = 0; nt < 16; nt++) {
        const int nc = n0 + wn * 128 + nt * 8 + 2 * cq;
        float bo0 = b_out[nc], bo1 = b_out[nc + 1];
        float e00 = fast_exp(acc[nt][0] + bo0);
        float e01 = fast_exp(acc[nt][1] + bo1);
        float e10 = fast_exp(acc[nt][2] + bo0);
        float e11 = fast_exp(acc[nt][3] + bo1);
        acc[nt][0] = e00; acc[nt][1] = e01; acc[nt][2] = e10; acc[nt][3] = e11;
        s0 += e00 + e01;  s1 += e10 + e11;
        m0v = fmaxf(m0v, fmaxf(e00, e01));
        m1v = fmaxf(m1v, fmaxf(e10, e11));
    }
#pragma unroll
    for (int o = 1; o <= 2; o <<= 1) {
        s0 += __shfl_xor_sync(0xFFFFFFFFu, s0, o);
        s1 += __shfl_xor_sync(0xFFFFFFFFu, s1, o);
        m0v = fmaxf(m0v, __shfl_xor_sync(0xFFFFFFFFu, m0v, o));
        m1v = fmaxf(m1v, __shfl_xor_sync(0xFFFFFFFFu, m1v, o));
    }
    if (cq == 0) {
        atomicAdd(&ssum[m0], s0);
        atomicAdd(&ssum[m0 + 8], s1);
        atomicMax(&smax[m0], __float_as_uint(m0v));
        atomicMax(&smax[m0 + 8], __float_as_uint(m1v));
    }
    __syncthreads();

    // global reduction with completion-forcing returns
    float retf = 0.0f; unsigned retu = 0u;
    if (tid < 64) {
        retf = atomicAdd(&g_sum[tid], ssum[tid]);
        retu = atomicMax(&g_maxe[tid], smax[tid]);
    }
    // consume the returns (data-dependent no-op) so the atomics are complete here
    if (tid < 64 && (__float_as_uint(retf) ^ retu) == 0x13572468u) ssum[tid] += 1.0f;
    __syncthreads();

    // converge all 125 blocks (all co-resident: 92 KB smem, 125 <= 148 SMs)
    if (tid == 0) {
        atomicAdd(&g_k2cnt, 1u);
        const unsigned target = 125u * (unsigned)(t + 1);
        unsigned v;
        do {
            asm volatile("ld.acquire.gpu.global.u32 %0, [%1];" : "=r"(v) : "l"(&g_k2cnt) : "memory");
        } while (v < target);
    }
    __syncthreads();

    // epilogue part 2: scale registers, write probs directly, collect candidates
    const float inv0 = 1.0f / g_sum[m0];
    const float inv1 = 1.0f / g_sum[m0 + 8];
    const float th0 = __uint_as_float(g_maxe[m0]) * 0.99f;
    const float th1 = __uint_as_float(g_maxe[m0 + 8]) * 0.99f;
    float* orow0 = out + (size_t)m0 * TT * VOC + (size_t)t * VOC;
    float* orow1 = out + (size_t)(m0 + 8) * TT * VOC + (size_t)t * VOC;
#pragma unroll
    for (int nt = 0; nt < 16; nt++) {
        const int nc = n0 + wn * 128 + nt * 8 + 2 * cq;
        float e00 = acc[nt][0], e01 = acc[nt][1], e10 = acc[nt][2], e11 = acc[nt][3];
        __stcs((float2*)&orow0[nc], make_float2(e00 * inv0, e01 * inv0));
        __stcs((float2*)&orow1[nc], make_float2(e10 * inv1, e11 * inv1));
        if (e00 > th0) { int p = atomicAdd(&g_ncand[m0], 1);     if (p < 32) g_cand[m0][p] = nc; }
        if (e01 > th0) { int p = atomicAdd(&g_ncand[m0], 1);     if (p < 32) g_cand[m0][p] = nc + 1; }
        if (e10 > th1) { int p = atomicAdd(&g_ncand[m0 + 8], 1); if (p < 32) g_cand[m0 + 8][p] = nc; }
        if (e11 > th1) { int p = atomicAdd(&g_ncand[m0 + 8], 1); if (p < 32) g_cand[m0 + 8][p] = nc + 1; }
    }
    cudaTriggerProgrammaticLaunchCompletion();
}

// ---------- K3: exact argmax rescue + prediction + x gather (tiny, PDL) ----------
__global__ __launch_bounds__(1024) void softmax_kernel(
        float* __restrict__ out, const float* __restrict__ Wout,
        const float* __restrict__ b_out, const float* __restrict__ emb,
        int t, int wp, int rd) {
    __shared__ float red[32];
    __shared__ float hbuf[1024];
    __shared__ int sbest;
    const int row = blockIdx.x;
    const int tid = threadIdx.x;
    const int lane = tid & 31, wid = tid >> 5;

    cudaGridDependencySynchronize();

    {
        const int seg = ((tid >> 3) & 7) * 8 + (tid & 7);
        const size_t hb = (((size_t)(rd * 16 + (tid >> 6))) * 2) * (64 * RP) + (size_t)row * RP + seg;
        hbuf[tid] = __bfloat162float(g_hblk[hb]) + __bfloat162float(g_hblk[hb + 64 * RP]);
    }
    __syncthreads();

    const int nc = min(g_ncand[row], 32);
    float bestv = -1e30f;
    int   besti = VOC;
    for (int i = 0; i < nc; i++) {
        const int v = g_cand[row][i];
        float part = hbuf[tid] * Wout[(size_t)v * HD + tid];
#pragma unroll
        for (int o = 16; o > 0; o >>= 1) part += __shfl_xor_sync(0xFFFFFFFFu, part, o);
        if (lane == 0) red[wid] = part;
        __syncthreads();
        if (tid < 32) {
            float pv = red[tid];
#pragma unroll
            for (int o = 16; o > 0; o >>= 1) pv += __shfl_xor_sync(0xFFFFFFFFu, pv, o);
            if (tid == 0) {
                float lg = pv + b_out[v];
                if (lg > bestv || (lg == bestv && v < besti)) { bestv = lg; besti = v; }
            }
        }
        __syncthreads();
    }

    if (tid == 0) {
        sbest = besti;
        g_ncand[row] = 0;
        g_sum[row] = 0.0f;
        g_maxe[row] = 0u;
        if (wp) out[(size_t)BATCH * TT * VOC + (size_t)row * TT + t] = (float)besti;
    }
    __syncthreads();

    {
        const int best = sbest;
        const int u = tid;
        float w = emb[(size_t)best * ED + u];
        __nv_bfloat16 hh = __float2bfloat16(w);
        const int seg = ((u >> 3) & 7) * 8 + (u & 7);
        const size_t xi = (((size_t)(u >> 6)) * 2) * (64 * RP) + (size_t)row * RP + seg;
        g_xblk[xi] = hh;
        g_xblk[xi + 64 * RP] = __float2bfloat16(w - __bfloat162float(hh));
    }
    cudaTriggerProgrammaticLaunchCompletion();
}

// ---------------- launch ----------------
extern "C" void kernel_launch(void* const* d_in, const int* in_sizes, int n_in,
                              void* d_out, int out_size) {
    const float* hidden = (const float*)d_in[0];
    const float* emb    = (const float*)d_in[1];
    const float* W_ih   = (const float*)d_in[2];
    const float* W_hh   = (const float*)d_in[3];
    const float* b_ih   = (const float*)d_in[4];
    const float* b_hh   = (const float*)d_in[5];
    const float* W_out  = (const float*)d_in[6];
    const float* b_out  = (const float*)d_in[7];
    float* out = (float*)d_out;
    const long long need_pred = (long long)BATCH * TT * VOC + (long long)BATCH * TT;
    int wp = ((long long)out_size >= need_pred) ? 1 : 0;

    const int k1_smem = 64 + 3 * K1_STAGE;   // 83008
    const int k2_smem = 64 + 2 * K2_STAGE;   // 92224
    cudaFuncSetAttribute(gates_kernel,  cudaFuncAttributeMaxDynamicSharedMemorySize, k1_smem);
    cudaFuncSetAttribute(logits_kernel, cudaFuncAttributeMaxDynamicSharedMemorySize, k2_smem);

    init_kernel<<<(BATCH * HD + 255) / 256, 256>>>(hidden, emb);
    split_kernel<<<2048, 256>>>(W_ih,  1, G4 * ED);
    split_kernel<<<2048, 256>>>(W_hh,  2, G4 * HD);
    split_kernel<<<4096, 256>>>(W_out, 3, VOC * HD);

    cudaLaunchAttribute pdl[1];
    pdl[0].id = cudaLaunchAttributeProgrammaticStreamSerialization;
    pdl[0].val.programmaticStreamSerializationAllowed = 1;

    for (int t = 0; t < TT; t++) {
        const int rd = t & 1;
        const int wb = rd ^ 1;

        {
            cudaLaunchConfig_t cfg = {};
            cfg.gridDim = dim3(128, 1, 1);
            cfg.blockDim = dim3(256, 1, 1);
            cfg.dynamicSmemBytes = (size_t)k1_smem;
            cfg.stream = 0;
            cfg.attrs = pdl; cfg.numAttrs = 1;
            cudaLaunchKernelEx(&cfg, gates_kernel, b_ih, b_hh, rd, wb);
        }
        {
            cudaLaunchConfig_t cfg = {};
            cfg.gridDim = dim3(125, 1, 1);
            cfg.blockDim = dim3(256, 1, 1);
            cfg.dynamicSmemBytes = (size_t)k2_smem;
            cfg.stream = 0;
            cfg.attrs = pdl; cfg.numAttrs = 1;
            cudaLaunchKernelEx(&cfg, logits_kernel, b_out, out, t);
        }
        {
            cudaLaunchConfig_t cfg = {};
            cfg.gridDim = dim3(BATCH, 1, 1);
            cfg.blockDim = dim3(1024, 1, 1);
            cfg.dynamicSmemBytes = 0;
            cfg.stream = 0;
            cfg.attrs = pdl; cfg.numAttrs = 1;
            cudaLaunchKernelEx(&cfg, softmax_kernel, out, W_out, b_out, emb, t, wp, wb);
        }
    }
    (void)in_sizes; (void)n_in;
}

// round 15
// speedup vs baseline: 1.2133x; 1.2133x over previous
#include <cuda_runtime.h>
#include <cuda_bf16.h>
#include <cuda_fp16.h>
#include <math.h>
#include <stdint.h>

#define BATCH 64
#define HD    1024
#define ED    1024
#define VOC   32000
#define TT    50
#define G4    (4*HD)
#define START_IDX 1

// row padded to 72 halves = 144 bytes (16B-aligned, conflict-free ldmatrix)
#define RP 72

// ---------------- device scratch ----------------
__device__ __align__(128) __nv_bfloat16 g_WB1[(size_t)128*32*2*32*RP];
__device__ __align__(128) __half        g_Wo16blk[(size_t)125*16*256*RP];
__device__ __align__(128) __nv_bfloat16 g_hblk[(size_t)2*16*2*64*RP];
__device__ __align__(128) __half        g_h16blk[(size_t)16*64*RP];
__device__ __align__(128) __nv_bfloat16 g_xblk[(size_t)16*2*64*RP];
__device__ float    g_c[BATCH*HD];
__device__ float    g_logits[BATCH*VOC];   // holds exp(logit) after K2
__device__ float    g_sum[BATCH];
__device__ unsigned g_maxe[BATCH];
__device__ unsigned long long g_best[BATCH];
__device__ int      g_done[BATCH];

// ---------------- asm helpers ----------------
__device__ __forceinline__ void mma_bf(float* c, const uint32_t* a, uint32_t b0, uint32_t b1) {
    asm volatile(
        "mma.sync.aligned.m16n8k16.row.col.f32.bf16.bf16.f32 "
        "{%0,%1,%2,%3}, {%4,%5,%6,%7}, {%8,%9}, {%0,%1,%2,%3};\n"
        : "+f"(c[0]), "+f"(c[1]), "+f"(c[2]), "+f"(c[3])
        : "r"(a[0]), "r"(a[1]), "r"(a[2]), "r"(a[3]), "r"(b0), "r"(b1));
}
__device__ __forceinline__ void mma_f16(float* c, const uint32_t* a, uint32_t b0, uint32_t b1) {
    asm volatile(
        "mma.sync.aligned.m16n8k16.row.col.f32.f16.f16.f32 "
        "{%0,%1,%2,%3}, {%4,%5,%6,%7}, {%8,%9}, {%0,%1,%2,%3};\n"
        : "+f"(c[0]), "+f"(c[1]), "+f"(c[2]), "+f"(c[3])
        : "r"(a[0]), "r"(a[1]), "r"(a[2]), "r"(a[3]), "r"(b0), "r"(b1));
}
__device__ __forceinline__ void ldsm4(uint32_t* r, uint32_t addr) {
    asm volatile("ldmatrix.sync.aligned.m8n8.x4.shared.b16 {%0,%1,%2,%3}, [%4];\n"
        : "=r"(r[0]), "=r"(r[1]), "=r"(r[2]), "=r"(r[3]) : "r"(addr));
}
__device__ __forceinline__ void bulk_g2s(uint32_t dst, const void* src, uint32_t bytes, uint32_t mbar) {
    asm volatile("cp.async.bulk.shared::cluster.global.mbarrier::complete_tx::bytes [%0], [%1], %2, [%3];\n"
        :: "r"(dst), "l"(src), "r"(bytes), "r"(mbar) : "memory");
}
// with an L2 cache policy (createpolicy) attached
__device__ __forceinline__ void bulk_g2s_pol(uint32_t dst, const void* src, uint32_t bytes,
                                             uint32_t mbar, uint64_t pol) {
    asm volatile("cp.async.bulk.shared::cluster.global.mbarrier::complete_tx::bytes.L2::cache_hint "
                 "[%0], [%1], %2, [%3], %4;\n"
        :: "r"(dst), "l"(src), "r"(bytes), "r"(mbar), "l"(pol) : "memory");
}
__device__ __forceinline__ uint64_t mkpol_evict_last() {
    uint64_t p;
    asm("createpolicy.fractional.L2::evict_last.b64 %0, 1.0;" : "=l"(p));
    return p;
}
__device__ __forceinline__ uint64_t mkpol_evict_first() {
    uint64_t p;
    asm("createpolicy.fractional.L2::evict_first.b64 %0, 1.0;" : "=l"(p));
    return p;
}
__device__ __forceinline__ void mbar_init(uint32_t a, uint32_t cnt) {
    asm volatile("mbarrier.init.shared.b64 [%0], %1;" :: "r"(a), "r"(cnt) : "memory");
}
__device__ __forceinline__ void mbar_expect(uint32_t a, uint32_t bytes) {
    asm volatile("mbarrier.arrive.expect_tx.shared.b64 _, [%0], %1;" :: "r"(a), "r"(bytes) : "memory");
}
__device__ __forceinline__ void mbar_wait(uint32_t a, uint32_t parity) {
    asm volatile(
        "{\n\t"
        ".reg .pred P1;\n\t"
        "WAIT_%=:\n\t"
        "mbarrier.try_wait.parity.acquire.cta.shared::cta.b64 P1, [%0], %1, 0x989680;\n\t"
        "@P1 bra.uni DONE_%=;\n\t"
        "bra.uni WAIT_%=;\n\t"
        "DONE_%=:\n\t"
        "}"
        :: "r"(a), "r"(parity) : "memory");
}
__device__ __forceinline__ void fence_async_init() {
    asm volatile("fence.proxy.async.shared::cta;" ::: "memory");
}

// FMA-only exp. rel err ~1.2e-7.
__device__ __forceinline__ float fast_exp(float x) {
    float t = x * 1.4426950408889634f;
    t = fmaxf(t, -120.0f);
    float n = rintf(t);
    float r = (t - n) * 0.6931471805599453f;
    float p = 1.0f / 5040.0f;
    p = fmaf(p, r, 1.0f / 720.0f);
    p = fmaf(p, r, 1.0f / 120.0f);
    p = fmaf(p, r, 1.0f / 24.0f);
    p = fmaf(p, r, 1.0f / 6.0f);
    p = fmaf(p, r, 0.5f);
    p = fmaf(p, r, 1.0f);
    p = fmaf(p, r, 1.0f);
    float s = __int_as_float(((int)n + 127) << 23);
    return p * s;
}

// ---------------- one-time weight prep ----------------
__global__ void split_kernel(const float* __restrict__ src, int which, int n) {
    int i = blockIdx.x * blockDim.x + threadIdx.x;
    int stride = gridDim.x * blockDim.x;
    if (which == 3) {          // W_out -> fp16 blocked [nb][chunk][256][RP]
        for (; i < n; i += stride) {
            int v = i >> 10, k = i & 1023;
            int nb = v >> 8, r = v & 255;
            size_t dst = ((size_t)(nb * 16 + (k >> 6)) * 256 + r) * RP
                       + ((k >> 3) & 7) * 8 + (k & 7);
            g_Wo16blk[dst] = __float2half(src[i]);
        }
    } else {                   // W_ih (1) / W_hh (2) -> bf16 hi/lo blocked
        const int cbase = (which == 1) ? 0 : 16;
        for (; i < n; i += stride) {
            int g = i >> 10, k = i & 1023;
            int gate = g >> 10, unit = g & 1023;
            int ublk = unit >> 3, rowB = (gate << 3) | (unit & 7);
            int c = cbase + (k >> 6);
            size_t baseidx = (((size_t)ublk * 32 + c) * 2) * (32 * RP)
                           + rowB * RP + ((k >> 3) & 7) * 8 + (k & 7);
            float w = src[i];
            __nv_bfloat16 h = __float2bfloat16(w);
            g_WB1[baseidx] = h;
            g_WB1[baseidx + 32 * RP] = __float2bfloat16(w - __bfloat162float(h));
        }
    }
}

__global__ void init_kernel(const float* __restrict__ hidden, const float* __restrict__ emb) {
    int i = blockIdx.x * blockDim.x + threadIdx.x;
    if (i < BATCH) { g_sum[i] = 0.0f; g_maxe[i] = 0u; g_best[i] = 0ull; g_done[i] = 0; }
    if (i < BATCH * HD) {
        int b = i >> 10, u = i & 1023;
        const int seg = ((u >> 3) & 7) * 8 + (u & 7);
        {
            float h = hidden[i];
            __nv_bfloat16 hh = __float2bfloat16(h);
            size_t idx = (((size_t)(u >> 6)) * 2) * (64 * RP) + (size_t)b * RP + seg;
            g_hblk[idx] = hh;
            g_hblk[idx + 64 * RP] = __float2bfloat16(h - __bfloat162float(hh));
        }
        {
            float w = emb[(size_t)START_IDX * ED + u];
            __nv_bfloat16 hh = __float2bfloat16(w);
            size_t idx = (((size_t)(u >> 6)) * 2) * (64 * RP) + (size_t)b * RP + seg;
            g_xblk[idx] = hh;
            g_xblk[idx + 64 * RP] = __float2bfloat16(w - __bfloat162float(hh));
        }
        g_c[i] = 0.0f;
    }
}

// ---------------- K1: gates GEMM + LSTM cell (256 thr, chunk=64, 3-stage, PDL) --
// stage layout (bytes): A(hi|lo) 18432 | B(hi|lo) 9216 = 27648 -> 3 stages = 83 KB
#define K1_STAGE 27648
__global__ __launch_bounds__(256) void gates_kernel(
        const float* __restrict__ b_ih, const float* __restrict__ b_hh,
        int rd, int wb) {
    extern __shared__ __align__(128) char dynsm[];
    const uint32_t base = (uint32_t)__cvta_generic_to_shared(dynsm);
    __shared__ float Cs[64][33];

    const int tid = threadIdx.x;
    const int ublk = blockIdx.x;
    const int u0 = ublk * 8;
    if (tid == 0) {
        mbar_init(base + 0, 1);
        mbar_init(base + 8, 1);
        mbar_init(base + 16, 1);
    }
    fence_async_init();
    __syncthreads();

    const int lane = tid & 31, wid = tid >> 5;
    const int gq = lane >> 2, cq = lane & 3;
    const int wm = wid & 3, wn = wid >> 2;
    const int lt = lane >> 3, lr = lane & 7;

    const uint64_t pol_first = mkpol_evict_first();

    float acc[2][4];
#pragma unroll
    for (int i = 0; i < 2; i++)
#pragma unroll
        for (int j = 0; j < 4; j++) acc[i][j] = 0.0f;

    auto issueB = [&](int c, int s) {
        const uint32_t st = base + 64u + (uint32_t)s * K1_STAGE;
        bulk_g2s_pol(st + 18432u,
                 (const char*)g_WB1 + ((size_t)(ublk * 32 + c)) * 9216u,
                 9216u, base + (uint32_t)s * 8u, pol_first);
    };
    auto issueA = [&](int c, int s) {
        const uint32_t st = base + 64u + (uint32_t)s * K1_STAGE;
        const char* asrc = (c < 16)
            ? (const char*)g_xblk + (size_t)c * 18432u
            : (const char*)g_hblk + ((size_t)(rd * 16 + (c - 16))) * 18432u;
        bulk_g2s(st, asrc, 18432u, base + (uint32_t)s * 8u);
    };
    auto issue = [&](int c, int s) {
        mbar_expect(base + (uint32_t)s * 8u, 27648u);
        issueA(c, s);
        issueB(c, s);
    };

    const int NIT = 32;
    // PDL prologue: prefetch weight tiles before syncing on predecessor
    if (tid == 0) {
#pragma unroll
        for (int s = 0; s < 3; s++) {
            mbar_expect(base + (uint32_t)s * 8u, 27648u);
            issueB(s, s);
        }
    }
    cudaGridDependencySynchronize();
    if (tid == 0) {
#pragma unroll
        for (int s = 0; s < 3; s++) issueA(s, s);
    }

    const int a_row = wm * 16 + ((lt & 1) << 3) + lr;
    const int a_sh  = lt >> 1;

    for (int it = 0; it < NIT; it++) {
        const int s = it % 3;
        mbar_wait(base + (uint32_t)s * 8u, (uint32_t)((it / 3) & 1));

        const uint32_t st = base + 64u + (uint32_t)s * K1_STAGE;
        const uint32_t Ahb = st, Alb = st + 9216u, Bhb = st + 18432u, Blb = st + 23040u;
        const uint32_t aoff = (uint32_t)(a_row * 144);

#pragma unroll
        for (int ktp = 0; ktp < 2; ktp++) {
            uint32_t h0[4], h1[4], l0[4], l1[4];
            const uint32_t s0 = (uint32_t)((4 * ktp + a_sh) * 16);
            const uint32_t s1 = (uint32_t)((4 * ktp + 2 + a_sh) * 16);
            ldsm4(h0, Ahb + aoff + s0);
            ldsm4(h1, Ahb + aoff + s1);
            ldsm4(l0, Alb + aoff + s0);
            ldsm4(l1, Alb + aoff + s1);
#pragma unroll
            for (int nt = 0; nt < 2; nt++) {
                const int rowB = wn * 16 + nt * 8 + lr;
                const uint32_t boff = (uint32_t)(rowB * 144 + (ktp * 4 + lt) * 16);
                uint32_t bh[4], bl[4];
                ldsm4(bh, Bhb + boff);
                ldsm4(bl, Blb + boff);
                mma_bf(acc[nt], h0, bh[0], bh[1]);
                mma_bf(acc[nt], l0, bh[0], bh[1]);
                mma_bf(acc[nt], h0, bl[0], bl[1]);
                mma_bf(acc[nt], h1, bh[2], bh[3]);
                mma_bf(acc[nt], l1, bh[2], bh[3]);
                mma_bf(acc[nt], h1, bl[2], bl[3]);
            }
        }
        __syncthreads();
        if (it + 3 < NIT && tid == 0) issue(it + 3, s);
    }

    {
        const int m0 = wm * 16 + gq;
#pragma unroll
        for (int nt = 0; nt < 2; nt++) {
            const int nc = wn * 16 + nt * 8 + 2 * cq;
            Cs[m0][nc]         = acc[nt][0];
            Cs[m0][nc + 1]     = acc[nt][1];
            Cs[m0 + 8][nc]     = acc[nt][2];
            Cs[m0 + 8][nc + 1] = acc[nt][3];
        }
    }
    __syncthreads();

    for (int r = tid; r < 64 * 8; r += 256) {
        const int b = r >> 3, uu = r & 7;
        const int u = u0 + uu;
        float iv = Cs[b][uu]      + b_ih[u]          + b_hh[u];
        float fv = Cs[b][8 + uu]  + b_ih[HD + u]     + b_hh[HD + u];
        float gv = Cs[b][16 + uu] + b_ih[2 * HD + u] + b_hh[2 * HD + u];
        float ov = Cs[b][24 + uu] + b_ih[3 * HD + u] + b_hh[3 * HD + u];
        float co = g_c[b * HD + u];
        float si = 1.0f / (1.0f + expf(-iv));
        float sf = 1.0f / (1.0f + expf(-fv));
        float so = 1.0f / (1.0f + expf(-ov));
        float cn = sf * co + si * tanhf(gv);
        float hn = so * tanhf(cn);
        g_c[b * HD + u] = cn;
        __nv_bfloat16 hh = __float2bfloat16(hn);
        const int seg = ((u >> 3) & 7) * 8 + (u & 7);
        const size_t hbase = (((size_t)(wb * 16 + (u >> 6))) * 2) * (64 * RP) + (size_t)b * RP + seg;
        g_hblk[hbase] = hh;
        g_hblk[hbase + 64 * RP] = __float2bfloat16(hn - __bfloat162float(hh));
        g_h16blk[((size_t)(u >> 6) * 64 + b) * RP + seg] = __float2half(hn);
    }
    cudaTriggerProgrammaticLaunchCompletion();
}

// ---------------- K2: logits GEMM + fused exp + row sum/max (256 thr, 2-stage) --
// 125 blocks x N=256, chunk 64, 2-stage. stage: A 9216 | B 36864 = 46080 -> 92 KB
#define K2_STAGE 46080
__global__ __launch_bounds__(256) void logits_kernel(
        const float* __restrict__ b_out) {
    extern __shared__ __align__(128) char dynsm2[];
    const uint32_t base = (uint32_t)__cvta_generic_to_shared(dynsm2);
    __shared__ float    ssum[64];
    __shared__ unsigned smax[64];

    const int tid = threadIdx.x;
    const int nb = blockIdx.x;
    const int n0 = nb * 256;
    const int lane = tid & 31, wid = tid >> 5;
    const int gq = lane >> 2, cq = lane & 3;
    const int wm = wid & 3, wn = wid >> 2;
    const int lt = lane >> 3, lr = lane & 7;

    if (tid == 0) {
        mbar_init(base + 0, 1);
        mbar_init(base + 8, 1);
    }
    if (tid < 64) { ssum[tid] = 0.0f; smax[tid] = 0u; }
    fence_async_init();
    __syncthreads();

    const uint64_t pol_last = mkpol_evict_last();

    float acc[16][4];
#pragma unroll
    for (int i = 0; i < 16; i++)
#pragma unroll
        for (int j = 0; j < 4; j++) acc[i][j] = 0.0f;

    auto issueW = [&](int c, int s) {
        const uint32_t st = base + 64u + (uint32_t)s * K2_STAGE;
        bulk_g2s_pol(st + 9216u,
                 (const char*)g_Wo16blk + ((size_t)(nb * 16 + c) * 256 * RP) * 2,
                 36864u, base + (uint32_t)s * 8u, pol_last);
    };
    auto issueH = [&](int c, int s) {
        const uint32_t st = base + 64u + (uint32_t)s * K2_STAGE;
        bulk_g2s(st, (const char*)g_h16blk + ((size_t)c * 64 * RP) * 2,
                 9216u, base + (uint32_t)s * 8u);
    };
    auto issue = [&](int c, int s) {
        mbar_expect(base + (uint32_t)s * 8u, 46080u);
        issueH(c, s);
        issueW(c, s);
    };

    const int NIT = 16;
    // PDL prologue: prefetch W_out tiles before syncing on K1's h
    if (tid == 0) {
#pragma unroll
        for (int s = 0; s < 2; s++) {
            mbar_expect(base + (uint32_t)s * 8u, 46080u);
            issueW(s, s);
        }
    }
    cudaGridDependencySynchronize();
    if (tid == 0) {
#pragma unroll
        for (int s = 0; s < 2; s++) issueH(s, s);
    }

    const int a_row = wm * 16 + ((lt & 1) << 3) + lr;
    const int a_sh  = lt >> 1;

    for (int it = 0; it < NIT; it++) {
        const int s = it & 1;
        mbar_wait(base + (uint32_t)s * 8u, (uint32_t)((it / 2) & 1));

        const uint32_t Ab = base + 64u + (uint32_t)s * K2_STAGE;
        const uint32_t Bb = Ab + 9216u;
        const uint32_t aoff = (uint32_t)(a_row * 144);

#pragma unroll
        for (int ktp = 0; ktp < 2; ktp++) {
            uint32_t a0[4], a1[4];
            ldsm4(a0, Ab + aoff + (uint32_t)((4 * ktp + a_sh) * 16));
            ldsm4(a1, Ab + aoff + (uint32_t)((4 * ktp + 2 + a_sh) * 16));
#pragma unroll
            for (int nt = 0; nt < 16; nt++) {
                const int rowB = wn * 128 + nt * 8 + lr;
                uint32_t b[4];
                ldsm4(b, Bb + (uint32_t)(rowB * 144 + (ktp * 4 + lt) * 16));
                mma_f16(acc[nt], a0, b[0], b[1]);
                mma_f16(acc[nt], a1, b[2], b[3]);
            }
        }
        __syncthreads();
        if (it + 2 < NIT && tid == 0) issue(it + 2, s);
    }

    // fused epilogue: exp, store e, reduce per-row sum/max
    const int m0 = wm * 16 + gq;
    float s0 = 0.0f, s1 = 0.0f;
    float m0v = 0.0f, m1v = 0.0f;
#pragma unroll
    for (int nt = 0; nt < 16; nt++) {
        const int nc = n0 + wn * 128 + nt * 8 + 2 * cq;
        float bo0 = b_out[nc], bo1 = b_out[nc + 1];
        float e00 = fast_exp(acc[nt][0] + bo0);
        float e01 = fast_exp(acc[nt][1] + bo1);
        float e10 = fast_exp(acc[nt][2] + bo0);
        float e11 = fast_exp(acc[nt][3] + bo1);
        *(float2*)&g_logits[m0 * VOC + nc]       = make_float2(e00, e01);
        *(float2*)&g_logits[(m0 + 8) * VOC + nc] = make_float2(e10, e11);
        s0 += e00 + e01;  s1 += e10 + e11;
        m0v = fmaxf(m0v, fmaxf(e00, e01));
        m1v = fmaxf(m1v, fmaxf(e10, e11));
    }
#pragma unroll
    for (int o = 1; o <= 2; o <<= 1) {
        s0 += __shfl_xor_sync(0xFFFFFFFFu, s0, o);
        s1 += __shfl_xor_sync(0xFFFFFFFFu, s1, o);
        m0v = fmaxf(m0v, __shfl_xor_sync(0xFFFFFFFFu, m0v, o));
        m1v = fmaxf(m1v, __shfl_xor_sync(0xFFFFFFFFu, m1v, o));
    }
    if (cq == 0) {
        atomicAdd(&ssum[m0], s0);
        atomicAdd(&ssum[m0 + 8], s1);
        atomicMax(&smax[m0], __float_as_uint(m0v));
        atomicMax(&smax[m0 + 8], __float_as_uint(m1v));
    }
    __syncthreads();
    if (tid < 64) {
        atomicAdd(&g_sum[tid], ssum[tid]);
        atomicMax(&g_maxe[tid], smax[tid]);
    }
    cudaTriggerProgrammaticLaunchCompletion();
}

// ---------- K3: 128 blocks (2 per row) scale+write + exact argmax + x gather ------
__global__ __launch_bounds__(1024) void softmax_kernel(
        float* __restrict__ out, const float* __restrict__ Wout,
        const float* __restrict__ b_out, const float* __restrict__ emb,
        int t, int wp, int rd) {
    __shared__ float red[32];
    __shared__ float hbuf[1024];
    __shared__ int cand[64];
    __shared__ int ncand;
    __shared__ int slast;
    __shared__ int sbest;
    const int bidx = blockIdx.x;
    const int row = bidx >> 1;
    const int half = bidx & 1;
    const int v0 = half * (VOC / 2);
    const int tid = threadIdx.x;
    const int lane = tid & 31, wid = tid >> 5;
    const float* lrow = g_logits + row * VOC;   // holds e = exp(logit)

    cudaGridDependencySynchronize();

    if (tid == 0) ncand = 0;
    const float inv = 1.0f / g_sum[row];
    const float thresh = __uint_as_float(g_maxe[row]) * 0.99f;

    {
        const int seg = ((tid >> 3) & 7) * 8 + (tid & 7);
        const size_t hb = (((size_t)(rd * 16 + (tid >> 6))) * 2) * (64 * RP) + (size_t)row * RP + seg;
        hbuf[tid] = __bfloat162float(g_hblk[hb]) + __bfloat162float(g_hblk[hb + 64 * RP]);
    }
    __syncthreads();

    float* orow = out + (size_t)row * TT * VOC + (size_t)t * VOC;
    for (int v = v0 + tid; v < v0 + VOC / 2; v += 1024) {
        float e = __ldcs(&lrow[v]);
        __stcs(&orow[v], e * inv);
        if (e > thresh) {
            int p = atomicAdd(&ncand, 1);
            if (p < 64) cand[p] = v;
        }
    }
    __syncthreads();

    const int nc = min(ncand, 64);
    float bestv = -1e30f;
    int   besti = VOC;
    for (int i = 0; i < nc; i++) {
        const int v = cand[i];
        float part = hbuf[tid] * Wout[(size_t)v * HD + tid];
#pragma unroll
        for (int o = 16; o > 0; o >>= 1) part += __shfl_xor_sync(0xFFFFFFFFu, part, o);
        if (lane == 0) red[wid] = part;
        __syncthreads();
        if (tid < 32) {
            float pv = red[tid];
#pragma unroll
            for (int o = 16; o > 0; o >>= 1) pv += __shfl_xor_sync(0xFFFFFFFFu, pv, o);
            if (tid == 0) {
                float lg = pv + b_out[v];
                if (lg > bestv || (lg == bestv && v < besti)) { bestv = lg; besti = v; }
            }
        }
        __syncthreads();
    }

    // merge the two halves: order-invariant packed atomicMax key
    if (tid == 0) {
        if (besti < VOC) {
            uint32_t bbits = __float_as_uint(bestv);
            uint32_t mono = (bbits & 0x80000000u) ? ~bbits : (bbits | 0x80000000u);
            unsigned long long key = ((unsigned long long)mono << 32)
                                   | (uint32_t)(~(uint32_t)besti);
            atomicMax(&g_best[row], key);
        }
        __threadfence();
        int old = atomicAdd(&g_done[row], 1);
        slast = (old == 1);
    }
    __syncthreads();

    if (slast) {
        if (tid == 0) {
            unsigned long long key = atomicAdd(&g_best[row], 0ull);
            int best = (int)(~(uint32_t)(key & 0xFFFFFFFFull));
            sbest = best;
            g_best[row] = 0ull;
            g_done[row] = 0;
            g_sum[row] = 0.0f;
            g_maxe[row] = 0u;
            if (wp) out[(size_t)BATCH * TT * VOC + (size_t)row * TT + t] = (float)best;
        }
        __syncthreads();
        {
            const int best = sbest;
            const int u = tid;
            float w = emb[(size_t)best * ED + u];
            __nv_bfloat16 hh = __float2bfloat16(w);
            const int seg = ((u >> 3) & 7) * 8 + (u & 7);
            const size_t xi = (((size_t)(u >> 6)) * 2) * (64 * RP) + (size_t)row * RP + seg;
            g_xblk[xi] = hh;
            g_xblk[xi + 64 * RP] = __float2bfloat16(w - __bfloat162float(hh));
        }
    }
    cudaTriggerProgrammaticLaunchCompletion();
}

// ---------------- launch ----------------
extern "C" void kernel_launch(void* const* d_in, const int* in_sizes, int n_in,
                              void* d_out, int out_size) {
    const float* hidden = (const float*)d_in[0];
    const float* emb    = (const float*)d_in[1];
    const float* W_ih   = (const float*)d_in[2];
    const float* W_hh   = (const float*)d_in[3];
    const float* b_ih   = (const float*)d_in[4];
    const float* b_hh   = (const float*)d_in[5];
    const float* W_out  = (const float*)d_in[6];
    const float* b_out  = (const float*)d_in[7];
    float* out = (float*)d_out;
    const long long need_pred = (long long)BATCH * TT * VOC + (long long)BATCH * TT;
    int wp = ((long long)out_size >= need_pred) ? 1 : 0;

    const int k1_smem = 64 + 3 * K1_STAGE;   // 83008
    const int k2_smem = 64 + 2 * K2_STAGE;   // 92224
    cudaFuncSetAttribute(gates_kernel,  cudaFuncAttributeMaxDynamicSharedMemorySize, k1_smem);
    cudaFuncSetAttribute(logits_kernel, cudaFuncAttributeMaxDynamicSharedMemorySize, k2_smem);

    init_kernel<<<(BATCH * HD + 255) / 256, 256>>>(hidden, emb);
    split_kernel<<<2048, 256>>>(W_ih,  1, G4 * ED);
    split_kernel<<<2048, 256>>>(W_hh,  2, G4 * HD);
    split_kernel<<<4096, 256>>>(W_out, 3, VOC * HD);

    cudaLaunchAttribute pdl[1];
    pdl[0].id = cudaLaunchAttributeProgrammaticStreamSerialization;
    pdl[0].val.programmaticStreamSerializationAllowed = 1;

    for (int t = 0; t < TT; t++) {
        const int rd = t & 1;
        const int wb = rd ^ 1;

        {
            cudaLaunchConfig_t cfg = {};
            cfg.gridDim = dim3(128, 1, 1);
            cfg.blockDim = dim3(256, 1, 1);
            cfg.dynamicSmemBytes = (size_t)k1_smem;
            cfg.stream = 0;
            cfg.attrs = pdl; cfg.numAttrs = 1;
            cudaLaunchKernelEx(&cfg, gates_kernel, b_ih, b_hh, rd, wb);
        }
        {
            cudaLaunchConfig_t cfg = {};
            cfg.gridDim = dim3(125, 1, 1);
            cfg.blockDim = dim3(256, 1, 1);
            cfg.dynamicSmemBytes = (size_t)k2_smem;
            cfg.stream = 0;
            cfg.attrs = pdl; cfg.numAttrs = 1;
            cudaLaunchKernelEx(&cfg, logits_kernel, b_out);
        }
        {
            cudaLaunchConfig_t cfg = {};
            cfg.gridDim = dim3(2 * BATCH, 1, 1);
            cfg.blockDim = dim3(1024, 1, 1);
            cfg.dynamicSmemBytes = 0;
            cfg.stream = 0;
            cfg.attrs = pdl; cfg.numAttrs = 1;
            cudaLaunchKernelEx(&cfg, softmax_kernel, out, W_out, b_out, emb, t, wp, wb);
        }
    }
    (void)in_sizes; (void)n_in;
}